// round 14
// baseline (speedup 1.0000x reference)
#include <cuda_runtime.h>
#include <cuda_bf16.h>

#define B_ 16
#define N_ 1024
#define F_ 256
#define H_ 4
#define D_ 64
#define BH_ (B_*H_)
#define NEG_SLOPE 0.2f
#define LOG2E 1.4426950408889634f

// Scratch (allocation-free rule: __device__ globals)
__device__ float    g_Wh[(size_t)BH_ * N_ * D_];  // fp32 Wh (scores)
// tf32-bit Wh, interleaved for LDS.64 B-fragments:
// off(j,d) = (j>>3)*512 + d*8 + (j&3)*2 + ((j>>2)&1)   (per bh)
__device__ unsigned g_Wt[(size_t)BH_ * N_ * D_];
__device__ float g_s1[BH_ * N_];    // s1 * log2e
__device__ float g_s2[BH_ * N_];    // s2 * log2e
__device__ float g_m2[BH_];         // max over masked j of prescaled s2
// split-bf16 copies of h and W (hi + lo), filled by k_split
__device__ __nv_bfloat16 g_hA[(size_t)B_ * N_ * F_];
__device__ __nv_bfloat16 g_lA[(size_t)B_ * N_ * F_];
__device__ __nv_bfloat16 g_hW[F_ * F_];
__device__ __nv_bfloat16 g_lW[F_ * F_];

__device__ __forceinline__ float ex2f(float x) {
    float r; asm("ex2.approx.f32 %0, %1;" : "=f"(r) : "f"(x)); return r;
}
__device__ __forceinline__ unsigned cvt_tf32(float x) {
    unsigned r; asm("cvt.rna.tf32.f32 %0, %1;" : "=r"(r) : "f"(x)); return r;
}
__device__ __forceinline__ void cpa16(unsigned dst, const void* src) {
    asm volatile("cp.async.ca.shared.global [%0], [%1], 16;" :: "r"(dst), "l"(src));
}

#define MMA_BF16(d, a, b) asm volatile( \
    "mma.sync.aligned.m16n8k16.row.col.f32.bf16.bf16.f32 " \
    "{%0,%1,%2,%3}, {%4,%5,%6,%7}, {%8,%9}, {%0,%1,%2,%3};" \
    : "+f"((d)[0]), "+f"((d)[1]), "+f"((d)[2]), "+f"((d)[3]) \
    : "r"((a)[0]), "r"((a)[1]), "r"((a)[2]), "r"((a)[3]), \
      "r"((b)[0]), "r"((b)[1]))

// ---------------------------------------------------------------------------
// Kernel 0: one-shot split of h and W into bf16 hi/lo pairs.
// ---------------------------------------------------------------------------
#define NA4 ((size_t)B_ * N_ * F_ / 4)
#define NW4 ((size_t)F_ * F_ / 4)
__global__ __launch_bounds__(256) void k_split(const float* __restrict__ h,
                                               const float* __restrict__ W) {
    size_t t = (size_t)blockIdx.x * 256 + threadIdx.x;
    if (t >= NA4 + NW4) return;
    const float4* src; __nv_bfloat16 *dh, *dl; size_t idx;
    if (t < NA4) { src = (const float4*)h; dh = g_hA; dl = g_lA; idx = t; }
    else         { src = (const float4*)W; dh = g_hW; dl = g_lW; idx = t - NA4; }
    float4 v = src[idx];
    float f[4] = {v.x, v.y, v.z, v.w};
    union { __nv_bfloat16 b[4]; uint2 u; } ph, pl;
#pragma unroll
    for (int e = 0; e < 4; e++) {
        __nv_bfloat16 hi = __float2bfloat16(f[e]);
        ph.b[e] = hi;
        pl.b[e] = __float2bfloat16(f[e] - __bfloat162float(hi));
    }
    *(uint2*)(dh + idx * 4) = ph.u;
    *(uint2*)(dl + idx * 4) = pl.u;
}

// ---------------------------------------------------------------------------
// Kernel A (tensor cores, cp.async pipelined): Wh = h @ W^T, split-bf16.
// Epilogue dual-stores fp32 Wh (scores) and interleaved tf32-bit Wh (attn).
// ---------------------------------------------------------------------------
#define KP 24
#define SZ_A (128 * KP * 2)
#define SZ_B (64 * KP * 2)
#define OFF_AH 0
#define OFF_AL (2 * SZ_A)
#define OFF_BH (4 * SZ_A)
#define OFF_BL (4 * SZ_A + 2 * SZ_B)
__global__ __launch_bounds__(256) void k_gemm_tc(const float* __restrict__ hun,
                                                 const float* __restrict__ Wun) {
    __shared__ __align__(16) char smem[4 * SZ_A + 4 * SZ_B];

    const int tid  = threadIdx.x;
    const int warp = tid >> 5, lane = tid & 31;
    const int g  = lane >> 2;
    const int tg = lane & 3;
    const int wm = warp >> 1;
    const int wn = warp & 1;
    const int m0 = blockIdx.x * 128;
    const int head = blockIdx.y;
    const unsigned sb = (unsigned)__cvta_generic_to_shared(smem);

    const int ar = tid >> 1,  ac = tid & 1;
    const int br = tid >> 2;
    const int bc = (tid >> 1) & 1, bl = tid & 1;
    const __nv_bfloat16* srcAh = g_hA + (size_t)(m0 + ar) * F_ + ac * 8;
    const __nv_bfloat16* srcAl = g_lA + (size_t)(m0 + ar) * F_ + ac * 8;
    const __nv_bfloat16* srcB  = (bl ? g_lW : g_hW) + (size_t)(head * 64 + br) * F_ + bc * 8;
    const unsigned dA  = ar * (KP * 2) + ac * 16;
    const unsigned dB  = sb + (bl ? OFF_BL : OFF_BH) + br * (KP * 2) + bc * 16;

#define FETCH(kt, buf) do {                                         \
        int ko = (kt) * 16;                                         \
        cpa16(sb + OFF_AH + (buf) * SZ_A + dA, srcAh + ko);         \
        cpa16(sb + OFF_AL + (buf) * SZ_A + dA, srcAl + ko);         \
        cpa16(dB + (buf) * SZ_B, srcB + ko);                        \
        asm volatile("cp.async.commit_group;");                     \
    } while (0)

    float acc[2][4][4];
#pragma unroll
    for (int mf = 0; mf < 2; mf++)
#pragma unroll
        for (int nf = 0; nf < 4; nf++)
#pragma unroll
            for (int q = 0; q < 4; q++) acc[mf][nf][q] = 0.f;

    FETCH(0, 0);
    FETCH(1, 1);

    for (int kt = 0; kt < 16; kt++) {
        const int buf = kt & 1;
        if (kt < 15) asm volatile("cp.async.wait_group 1;");
        else         asm volatile("cp.async.wait_group 0;");
        __syncthreads();

        const __nv_bfloat16* Ah = (const __nv_bfloat16*)(smem + OFF_AH + buf * SZ_A);
        const __nv_bfloat16* Al = (const __nv_bfloat16*)(smem + OFF_AL + buf * SZ_A);
        const __nv_bfloat16* Bh = (const __nv_bfloat16*)(smem + OFF_BH + buf * SZ_B);
        const __nv_bfloat16* Bl = (const __nv_bfloat16*)(smem + OFF_BL + buf * SZ_B);
        const int kb = 2 * tg;

        unsigned ah[2][4], al[2][4], bh[4][2], blf[4][2];
#pragma unroll
        for (int mf = 0; mf < 2; mf++) {
            const int base = (wm * 32 + mf * 16 + g) * KP;
            ah[mf][0] = *(const unsigned*)&Ah[base + kb];
            ah[mf][1] = *(const unsigned*)&Ah[base + 8 * KP + kb];
            ah[mf][2] = *(const unsigned*)&Ah[base + kb + 8];
            ah[mf][3] = *(const unsigned*)&Ah[base + 8 * KP + kb + 8];
            al[mf][0] = *(const unsigned*)&Al[base + kb];
            al[mf][1] = *(const unsigned*)&Al[base + 8 * KP + kb];
            al[mf][2] = *(const unsigned*)&Al[base + kb + 8];
            al[mf][3] = *(const unsigned*)&Al[base + 8 * KP + kb + 8];
        }
#pragma unroll
        for (int nf = 0; nf < 4; nf++) {
            const int bb = (wn * 32 + nf * 8 + g) * KP + kb;
            bh[nf][0]  = *(const unsigned*)&Bh[bb];
            bh[nf][1]  = *(const unsigned*)&Bh[bb + 8];
            blf[nf][0] = *(const unsigned*)&Bl[bb];
            blf[nf][1] = *(const unsigned*)&Bl[bb + 8];
        }
#pragma unroll
        for (int mf = 0; mf < 2; mf++)
#pragma unroll
            for (int nf = 0; nf < 4; nf++) {
                MMA_BF16(acc[mf][nf], ah[mf], bh[nf]);
                MMA_BF16(acc[mf][nf], al[mf], bh[nf]);
                MMA_BF16(acc[mf][nf], ah[mf], blf[nf]);
            }
        __syncthreads();
        if (kt + 2 < 16) FETCH(kt + 2, buf);
    }

    // scatter: fp32 -> g_Wh, tf32 bits -> g_Wt (interleaved layout)
#pragma unroll
    for (int mf = 0; mf < 2; mf++) {
        const int row0 = m0 + wm * 32 + mf * 16 + g;
        const int b = row0 >> 10, n = row0 & 1023;
        const size_t base  = ((size_t)(b * H_ + head) * N_ + n) * D_;
        const size_t tbase = (size_t)(b * H_ + head) * N_ * D_;
        unsigned* wp = g_Wt + tbase + (size_t)(n >> 3) * 512 + (n & 3) * 2 + ((n >> 2) & 1);
#pragma unroll
        for (int nf = 0; nf < 4; nf++) {
            const int d = wn * 32 + nf * 8 + 2 * tg;
            *(float2*)(g_Wh + base + d) = make_float2(acc[mf][nf][0], acc[mf][nf][1]);
            *(float2*)(g_Wh + base + 8 * D_ + d) = make_float2(acc[mf][nf][2], acc[mf][nf][3]);
            wp[d * 8]           = cvt_tf32(acc[mf][nf][0]);   // (n,   d)
            wp[d * 8 + 8]       = cvt_tf32(acc[mf][nf][1]);   // (n,   d+1)
            wp[512 + d * 8]     = cvt_tf32(acc[mf][nf][2]);   // (n+8, d)
            wp[512 + d * 8 + 8] = cvt_tf32(acc[mf][nf][3]);   // (n+8, d+1)
        }
    }
}

// ---------------------------------------------------------------------------
// Kernel B: prescaled s1,s2 (x log2e) per (bh,n) + masked max of s2'.
// ---------------------------------------------------------------------------
__global__ __launch_bounds__(256) void k_scores(const int* __restrict__ mask,
                                                const float* __restrict__ a) {
    __shared__ float sa[128];
    __shared__ float red[256];
    const int bh = blockIdx.x, b = bh >> 2, tid = threadIdx.x;
    if (tid < 128) sa[tid] = a[tid];
    __syncthreads();

    float lmax = -3.0e38f;
    for (int n = tid; n < N_; n += 256) {
        const float4* row = (const float4*)(g_Wh + ((size_t)bh * N_ + n) * D_);
        float s1 = 0.f, s2 = 0.f;
#pragma unroll
        for (int q = 0; q < 16; q++) {
            float4 v = row[q];
            s1 += v.x * sa[q*4+0] + v.y * sa[q*4+1] + v.z * sa[q*4+2] + v.w * sa[q*4+3];
            s2 += v.x * sa[64+q*4+0] + v.y * sa[64+q*4+1] + v.z * sa[64+q*4+2] + v.w * sa[64+q*4+3];
        }
        s1 *= LOG2E;
        s2 *= LOG2E;
        g_s1[bh * N_ + n] = s1;
        g_s2[bh * N_ + n] = s2;
        if (mask[b * N_ + n]) lmax = fmaxf(lmax, s2);
    }
    red[tid] = lmax;
    __syncthreads();
    for (int s = 128; s > 0; s >>= 1) {
        if (tid < s) red[tid] = fmaxf(red[tid], red[tid + s]);
        __syncthreads();
    }
    if (tid == 0) g_m2[bh] = red[0];
}

// ---------------------------------------------------------------------------
// Kernel C (tensor cores, cp.async pipelined): softmax(P) @ Wh.
// tf32 mma.m16n8k8. One m16 fragment per warp (32 accs/thread) -> low regs,
// 3 blocks/SM occupancy. grid (N/128=8, BH=64), block 256 (8 warps).
// ---------------------------------------------------------------------------
#define TJ 64
#define SZT (TJ * D_ * 4)   // 16384 bytes per buffer
__global__ __launch_bounds__(256, 3) void k_attn_tc(const int* __restrict__ mask,
                                                    float* __restrict__ out) {
    __shared__ __align__(16) unsigned sWh[2][TJ * D_];
    __shared__ __align__(8) float2 sS2[2][TJ];
    const int bh = blockIdx.y, b = bh >> 2, hh = bh & 3;
    const int tid = threadIdx.x;
    const int warp = tid >> 5, lane = tid & 31;
    const int g  = lane >> 2;
    const int tg = lane & 3;
    const int ib = blockIdx.x * 128;
    const unsigned sbW = (unsigned)__cvta_generic_to_shared(sWh);

    const float m2 = g_m2[bh];
    const bool m2ok = (m2 > -1.0e29f);

    int r0 = ib + warp * 16 + g;
    int rr[2] = { r0, r0 + 8 };

    float s1r[2], s1q[2];
    int   mrow[2];
#pragma unroll
    for (int q = 0; q < 2; q++) {
        float s1p = g_s1[bh * N_ + rr[q]];        // prescaled s1*log2e
        float t0 = s1p + m2;
        float rm = fmaxf(t0, NEG_SLOPE * t0);     // rowmax * log2e
        s1r[q] = s1p - rm;
        s1q[q] = fmaf(NEG_SLOPE, s1p, -rm);
        mrow[q] = mask[b * N_ + rr[q]];
    }

    const unsigned* WtB = g_Wt + (size_t)bh * N_ * D_;

#define FILLJ(tile, buf) do {                                              \
        const unsigned* srcW = WtB + (size_t)(tile) * TJ * D_;             \
        _Pragma("unroll")                                                  \
        for (int q = 0; q < 4; q++) {                                      \
            int id = tid + 256 * q;                                        \
            cpa16(sbW + (buf) * SZT + id * 16, srcW + id * 4);             \
        }                                                                  \
        asm volatile("cp.async.commit_group;");                            \
    } while (0)
#define FILLS(tile, buf) do {                                              \
        if (tid < TJ) {                                                    \
            int j = (tile) * TJ + tid;                                     \
            float v = mask[b * N_ + j] ? g_s2[bh * N_ + j] : -1.0e30f;     \
            sS2[buf][tid] = make_float2(v, NEG_SLOPE * v);                 \
        }                                                                  \
    } while (0)

    float acc[8][4];
#pragma unroll
    for (int nt = 0; nt < 8; nt++)
#pragma unroll
        for (int q = 0; q < 4; q++) acc[nt][q] = 0.f;
    float wsum[2] = {0.f, 0.f};

    FILLJ(0, 0);
    FILLJ(1, 1);
    FILLS(0, 0);
    FILLS(1, 1);

    for (int t = 0; t < N_ / TJ; t++) {
        const int buf = t & 1;
        if (t < N_ / TJ - 1) asm volatile("cp.async.wait_group 1;");
        else                 asm volatile("cp.async.wait_group 0;");
        __syncthreads();

        const unsigned* tile = sWh[buf];
        const float2*   sSt  = sS2[buf];

#pragma unroll 1
        for (int ks = 0; ks < TJ / 8; ks++) {
            const float2 qa = sSt[ks * 8 + tg];
            const float2 qb = sSt[ks * 8 + 4 + tg];

            // A fragment: rows {g, g+8}, k cols {tg, tg+4}
            float w0 = ex2f(fmaxf(s1r[0] + qa.x, s1q[0] + qa.y));
            float w1 = ex2f(fmaxf(s1r[1] + qa.x, s1q[1] + qa.y));
            float w2 = ex2f(fmaxf(s1r[0] + qb.x, s1q[0] + qb.y));
            float w3 = ex2f(fmaxf(s1r[1] + qb.x, s1q[1] + qb.y));
            wsum[0] += w0 + w2;
            wsum[1] += w1 + w3;
            unsigned af0 = __float_as_uint(w0) + 0x1000u;  // tf32 round (ALU)
            unsigned af1 = __float_as_uint(w1) + 0x1000u;
            unsigned af2 = __float_as_uint(w2) + 0x1000u;
            unsigned af3 = __float_as_uint(w3) + 0x1000u;

            // B fragments: one LDS.64 per nt gives (k=tg, k=tg+4) pair
            const uint2* bp = (const uint2*)(tile + ks * 512);
            uint2 bf[8];
#pragma unroll
            for (int nt = 0; nt < 8; nt++)
                bf[nt] = bp[(nt * 8 + g) * 4 + tg];

#pragma unroll
            for (int nt = 0; nt < 8; nt++) {
                asm volatile(
                    "mma.sync.aligned.m16n8k8.row.col.f32.tf32.tf32.f32 "
                    "{%0,%1,%2,%3}, {%4,%5,%6,%7}, {%8,%9}, {%0,%1,%2,%3};"
                    : "+f"(acc[nt][0]), "+f"(acc[nt][1]),
                      "+f"(acc[nt][2]), "+f"(acc[nt][3])
                    : "r"(af0), "r"(af1), "r"(af2), "r"(af3),
                      "r"(bf[nt].x), "r"(bf[nt].y));
            }
        }
        __syncthreads();
        if (t + 2 < N_ / TJ) {
            FILLJ(t + 2, buf);
            FILLS(t + 2, buf);
        }
    }

#pragma unroll
    for (int q = 0; q < 2; q++) {
        wsum[q] += __shfl_xor_sync(0xffffffffu, wsum[q], 1);
        wsum[q] += __shfl_xor_sync(0xffffffffu, wsum[q], 2);
    }

#pragma unroll
    for (int q = 0; q < 2; q++) {
        const bool good = mrow[q] && m2ok && (wsum[q] > 0.f);
        const float inv = 1.f / wsum[q];
        const int lohi = q * 2;
        float* op = out + ((size_t)(b * N_ + rr[q])) * (H_ * D_) + hh * D_ + tg * 2;
#pragma unroll
        for (int nt = 0; nt < 8; nt++) {
            float2 v;
            v.x = good ? acc[nt][lohi + 0] * inv : 0.f;
            v.y = good ? acc[nt][lohi + 1] * inv : 0.f;
            *(float2*)(op + nt * 8) = v;
        }
    }
}

// ---------------------------------------------------------------------------
extern "C" void kernel_launch(void* const* d_in, const int* in_sizes, int n_in,
                              void* d_out, int out_size) {
    const float* h    = (const float*)d_in[0];   // [16,1024,256] f32
    const int*   mask = (const int*)  d_in[1];   // [16,1024] i32
    const float* W    = (const float*)d_in[2];   // [256,256] f32
    const float* a    = (const float*)d_in[3];   // [128,1] f32
    float* out = (float*)d_out;                  // [16,1024,256] f32

    int nsplit = (int)((NA4 + NW4 + 255) / 256);
    k_split  <<<nsplit, 256>>>(h, W);
    k_gemm_tc<<<dim3(128, 4), 256>>>(h, W);
    k_scores <<<64, 256>>>(mask, a);
    k_attn_tc<<<dim3(N_ / 128, BH_), 256>>>(mask, out);
}

// round 15
// speedup vs baseline: 1.0681x; 1.0681x over previous
#include <cuda_runtime.h>
#include <cuda_bf16.h>

#define B_ 16
#define N_ 1024
#define F_ 256
#define H_ 4
#define D_ 64
#define BH_ (B_*H_)
#define NEG_SLOPE 0.2f
#define LOG2E 1.4426950408889634f

// Scratch (allocation-free rule: __device__ globals)
__device__ float    g_Wh[(size_t)BH_ * N_ * D_];  // fp32 Wh (scores)
// tf32-bit Wh, interleaved for LDS.64 B-fragments:
// off(j,d) = (j>>3)*512 + d*8 + (j&3)*2 + ((j>>2)&1)   (per bh)
__device__ unsigned g_Wt[(size_t)BH_ * N_ * D_];
__device__ float g_s1[BH_ * N_];    // s1 * log2e
__device__ float g_s2[BH_ * N_];    // s2 * log2e
__device__ float g_m2[BH_];         // max over masked j of prescaled s2
// split-bf16 copies of h and W (hi + lo), filled by k_split
__device__ __nv_bfloat16 g_hA[(size_t)B_ * N_ * F_];
__device__ __nv_bfloat16 g_lA[(size_t)B_ * N_ * F_];
__device__ __nv_bfloat16 g_hW[F_ * F_];
__device__ __nv_bfloat16 g_lW[F_ * F_];

__device__ __forceinline__ float ex2f(float x) {
    float r; asm("ex2.approx.f32 %0, %1;" : "=f"(r) : "f"(x)); return r;
}
__device__ __forceinline__ unsigned cvt_tf32(float x) {
    unsigned r; asm("cvt.rna.tf32.f32 %0, %1;" : "=r"(r) : "f"(x)); return r;
}
__device__ __forceinline__ void cpa16(unsigned dst, const void* src) {
    asm volatile("cp.async.ca.shared.global [%0], [%1], 16;" :: "r"(dst), "l"(src));
}

#define MMA_BF16(d, a, b) asm volatile( \
    "mma.sync.aligned.m16n8k16.row.col.f32.bf16.bf16.f32 " \
    "{%0,%1,%2,%3}, {%4,%5,%6,%7}, {%8,%9}, {%0,%1,%2,%3};" \
    : "+f"((d)[0]), "+f"((d)[1]), "+f"((d)[2]), "+f"((d)[3]) \
    : "r"((a)[0]), "r"((a)[1]), "r"((a)[2]), "r"((a)[3]), \
      "r"((b)[0]), "r"((b)[1]))

// ---------------------------------------------------------------------------
// Kernel 0: one-shot split of h and W into bf16 hi/lo pairs.
// ---------------------------------------------------------------------------
#define NA4 ((size_t)B_ * N_ * F_ / 4)
#define NW4 ((size_t)F_ * F_ / 4)
__global__ __launch_bounds__(256) void k_split(const float* __restrict__ h,
                                               const float* __restrict__ W) {
    size_t t = (size_t)blockIdx.x * 256 + threadIdx.x;
    if (t >= NA4 + NW4) return;
    const float4* src; __nv_bfloat16 *dh, *dl; size_t idx;
    if (t < NA4) { src = (const float4*)h; dh = g_hA; dl = g_lA; idx = t; }
    else         { src = (const float4*)W; dh = g_hW; dl = g_lW; idx = t - NA4; }
    float4 v = src[idx];
    float f[4] = {v.x, v.y, v.z, v.w};
    union { __nv_bfloat16 b[4]; uint2 u; } ph, pl;
#pragma unroll
    for (int e = 0; e < 4; e++) {
        __nv_bfloat16 hi = __float2bfloat16(f[e]);
        ph.b[e] = hi;
        pl.b[e] = __float2bfloat16(f[e] - __bfloat162float(hi));
    }
    *(uint2*)(dh + idx * 4) = ph.u;
    *(uint2*)(dl + idx * 4) = pl.u;
}

// ---------------------------------------------------------------------------
// Kernel A (tensor cores, 4-stage cp.async pipeline, one sync per k-chunk):
// Wh = h @ W^T, split-bf16 3-term MMA.
// grid (128, H=4), block 256 = 8 warps (4m x 2n). Tile M=128 N=64, K-chunk 16.
// Stage layout (18432 B): AH[128x24] AL[128x24] BH[64x24] BL[64x24] (bf16).
// Dynamic smem = 4 stages = 73728 B.
// ---------------------------------------------------------------------------
#define KP 24
#define STG_AH 0
#define STG_AL 6144
#define STG_BH 12288
#define STG_BL 15360
#define STG_SZ 18432
#define GEMM_SMEM (4 * STG_SZ)
__global__ __launch_bounds__(256) void k_gemm_tc(const float* __restrict__ hun,
                                                 const float* __restrict__ Wun) {
    extern __shared__ __align__(16) char smem[];

    const int tid  = threadIdx.x;
    const int warp = tid >> 5, lane = tid & 31;
    const int g  = lane >> 2;
    const int tg = lane & 3;
    const int wm = warp >> 1;
    const int wn = warp & 1;
    const int m0 = blockIdx.x * 128;
    const int head = blockIdx.y;
    const unsigned sb = (unsigned)__cvta_generic_to_shared(smem);

    const int ar = tid >> 1,  ac = tid & 1;          // A: 128 rows x 2 chunks
    const int br = tid >> 2;                         // B: 64 rows x 2 chunks x hi/lo
    const int bc = (tid >> 1) & 1, bl = tid & 1;
    const __nv_bfloat16* srcAh = g_hA + (size_t)(m0 + ar) * F_ + ac * 8;
    const __nv_bfloat16* srcAl = g_lA + (size_t)(m0 + ar) * F_ + ac * 8;
    const __nv_bfloat16* srcB  = (bl ? g_lW : g_hW) + (size_t)(head * 64 + br) * F_ + bc * 8;
    const unsigned dA  = ar * (KP * 2) + ac * 16;
    const unsigned dBo = STG_BH + bl * (STG_BL - STG_BH) + br * (KP * 2) + bc * 16;

#define FETCH(kt, st) do {                                          \
        int ko = (kt) * 16;                                         \
        unsigned base = sb + (unsigned)(st) * STG_SZ;               \
        cpa16(base + STG_AH + dA, srcAh + ko);                      \
        cpa16(base + STG_AL + dA, srcAl + ko);                      \
        cpa16(base + dBo, srcB + ko);                               \
        asm volatile("cp.async.commit_group;");                     \
    } while (0)

    float acc[2][4][4];
#pragma unroll
    for (int mf = 0; mf < 2; mf++)
#pragma unroll
        for (int nf = 0; nf < 4; nf++)
#pragma unroll
            for (int q = 0; q < 4; q++) acc[mf][nf][q] = 0.f;

    FETCH(0, 0);
    FETCH(1, 1);
    FETCH(2, 2);

    for (int kt = 0; kt < 16; kt++) {
        const int st = kt & 3;
        if (kt < 14)       asm volatile("cp.async.wait_group 2;");
        else if (kt == 14) asm volatile("cp.async.wait_group 1;");
        else               asm volatile("cp.async.wait_group 0;");
        __syncthreads();

        const char* stage = smem + st * STG_SZ;
        const __nv_bfloat16* Ah = (const __nv_bfloat16*)(stage + STG_AH);
        const __nv_bfloat16* Al = (const __nv_bfloat16*)(stage + STG_AL);
        const __nv_bfloat16* Bh = (const __nv_bfloat16*)(stage + STG_BH);
        const __nv_bfloat16* Bl = (const __nv_bfloat16*)(stage + STG_BL);
        const int kb = 2 * tg;

        unsigned ah[2][4], al[2][4], bh[4][2], blf[4][2];
#pragma unroll
        for (int mf = 0; mf < 2; mf++) {
            const int base = (wm * 32 + mf * 16 + g) * KP;
            ah[mf][0] = *(const unsigned*)&Ah[base + kb];
            ah[mf][1] = *(const unsigned*)&Ah[base + 8 * KP + kb];
            ah[mf][2] = *(const unsigned*)&Ah[base + kb + 8];
            ah[mf][3] = *(const unsigned*)&Ah[base + 8 * KP + kb + 8];
            al[mf][0] = *(const unsigned*)&Al[base + kb];
            al[mf][1] = *(const unsigned*)&Al[base + 8 * KP + kb];
            al[mf][2] = *(const unsigned*)&Al[base + kb + 8];
            al[mf][3] = *(const unsigned*)&Al[base + 8 * KP + kb + 8];
        }
#pragma unroll
        for (int nf = 0; nf < 4; nf++) {
            const int bb = (wn * 32 + nf * 8 + g) * KP + kb;
            bh[nf][0]  = *(const unsigned*)&Bh[bb];
            bh[nf][1]  = *(const unsigned*)&Bh[bb + 8];
            blf[nf][0] = *(const unsigned*)&Bl[bb];
            blf[nf][1] = *(const unsigned*)&Bl[bb + 8];
        }
#pragma unroll
        for (int mf = 0; mf < 2; mf++)
#pragma unroll
            for (int nf = 0; nf < 4; nf++) {
                MMA_BF16(acc[mf][nf], ah[mf], bh[nf]);
                MMA_BF16(acc[mf][nf], al[mf], bh[nf]);
                MMA_BF16(acc[mf][nf], ah[mf], blf[nf]);
            }
        // fetch into stage (kt-1)%4 — all warps finished reading it (sync above)
        if (kt + 3 < 16) FETCH(kt + 3, (kt + 3) & 3);
    }

    // scatter: fp32 -> g_Wh, tf32 bits -> g_Wt (interleaved layout)
#pragma unroll
    for (int mf = 0; mf < 2; mf++) {
        const int row0 = m0 + wm * 32 + mf * 16 + g;
        const int b = row0 >> 10, n = row0 & 1023;
        const size_t base  = ((size_t)(b * H_ + head) * N_ + n) * D_;
        const size_t tbase = (size_t)(b * H_ + head) * N_ * D_;
        unsigned* wp = g_Wt + tbase + (size_t)(n >> 3) * 512 + (n & 3) * 2 + ((n >> 2) & 1);
#pragma unroll
        for (int nf = 0; nf < 4; nf++) {
            const int d = wn * 32 + nf * 8 + 2 * tg;
            *(float2*)(g_Wh + base + d) = make_float2(acc[mf][nf][0], acc[mf][nf][1]);
            *(float2*)(g_Wh + base + 8 * D_ + d) = make_float2(acc[mf][nf][2], acc[mf][nf][3]);
            wp[d * 8]           = cvt_tf32(acc[mf][nf][0]);   // (n,   d)
            wp[d * 8 + 8]       = cvt_tf32(acc[mf][nf][1]);   // (n,   d+1)
            wp[512 + d * 8]     = cvt_tf32(acc[mf][nf][2]);   // (n+8, d)
            wp[512 + d * 8 + 8] = cvt_tf32(acc[mf][nf][3]);   // (n+8, d+1)
        }
    }
}

// ---------------------------------------------------------------------------
// Kernel B: prescaled s1,s2 (x log2e) per (bh,n) + masked max of s2'.
// ---------------------------------------------------------------------------
__global__ __launch_bounds__(256) void k_scores(const int* __restrict__ mask,
                                                const float* __restrict__ a) {
    __shared__ float sa[128];
    __shared__ float red[256];
    const int bh = blockIdx.x, b = bh >> 2, tid = threadIdx.x;
    if (tid < 128) sa[tid] = a[tid];
    __syncthreads();

    float lmax = -3.0e38f;
    for (int n = tid; n < N_; n += 256) {
        const float4* row = (const float4*)(g_Wh + ((size_t)bh * N_ + n) * D_);
        float s1 = 0.f, s2 = 0.f;
#pragma unroll
        for (int q = 0; q < 16; q++) {
            float4 v = row[q];
            s1 += v.x * sa[q*4+0] + v.y * sa[q*4+1] + v.z * sa[q*4+2] + v.w * sa[q*4+3];
            s2 += v.x * sa[64+q*4+0] + v.y * sa[64+q*4+1] + v.z * sa[64+q*4+2] + v.w * sa[64+q*4+3];
        }
        s1 *= LOG2E;
        s2 *= LOG2E;
        g_s1[bh * N_ + n] = s1;
        g_s2[bh * N_ + n] = s2;
        if (mask[b * N_ + n]) lmax = fmaxf(lmax, s2);
    }
    red[tid] = lmax;
    __syncthreads();
    for (int s = 128; s > 0; s >>= 1) {
        if (tid < s) red[tid] = fmaxf(red[tid], red[tid + s]);
        __syncthreads();
    }
    if (tid == 0) g_m2[bh] = red[0];
}

// ---------------------------------------------------------------------------
// Kernel C (tensor cores, cp.async pipelined): softmax(P) @ Wh.
// Round-13 configuration (best measured): 2 m-frags/warp, grid (N/256, BH).
// tf32 mma.m16n8k8, LDS.64 B-fragments from interleaved tiles.
// ---------------------------------------------------------------------------
#define TJ 64
#define SZT (TJ * D_ * 4)   // 16384 bytes per buffer
__global__ __launch_bounds__(256, 2) void k_attn_tc(const int* __restrict__ mask,
                                                    float* __restrict__ out) {
    __shared__ __align__(16) unsigned sWh[2][TJ * D_];
    __shared__ __align__(8) float2 sS2[2][TJ];
    const int bh = blockIdx.y, b = bh >> 2, hh = bh & 3;
    const int tid = threadIdx.x;
    const int warp = tid >> 5, lane = tid & 31;
    const int g  = lane >> 2;
    const int tg = lane & 3;
    const int ib = blockIdx.x * 256;
    const unsigned sbW = (unsigned)__cvta_generic_to_shared(sWh);

    const float m2 = g_m2[bh];
    const bool m2ok = (m2 > -1.0e29f);

    int r0 = ib + warp * 16 + g;
    int rr[4] = { r0, r0 + 8, r0 + 128, r0 + 136 };

    float s1r[4], s1q[4];
    int   mrow[4];
#pragma unroll
    for (int q = 0; q < 4; q++) {
        float s1p = g_s1[bh * N_ + rr[q]];        // prescaled s1*log2e
        float t0 = s1p + m2;
        float rm = fmaxf(t0, NEG_SLOPE * t0);     // rowmax * log2e
        s1r[q] = s1p - rm;
        s1q[q] = fmaf(NEG_SLOPE, s1p, -rm);
        mrow[q] = mask[b * N_ + rr[q]];
    }

    const unsigned* WtB = g_Wt + (size_t)bh * N_ * D_;

#define FILLJ(tile, buf) do {                                              \
        const unsigned* srcW = WtB + (size_t)(tile) * TJ * D_;             \
        _Pragma("unroll")                                                  \
        for (int q = 0; q < 4; q++) {                                      \
            int id = tid + 256 * q;                                        \
            cpa16(sbW + (buf) * SZT + id * 16, srcW + id * 4);             \
        }                                                                  \
        asm volatile("cp.async.commit_group;");                            \
    } while (0)
#define FILLS(tile, buf) do {                                              \
        if (tid < TJ) {                                                    \
            int j = (tile) * TJ + tid;                                     \
            float v = mask[b * N_ + j] ? g_s2[bh * N_ + j] : -1.0e30f;     \
            sS2[buf][tid] = make_float2(v, NEG_SLOPE * v);                 \
        }                                                                  \
    } while (0)

    float acc[2][8][4];
#pragma unroll
    for (int f = 0; f < 2; f++)
#pragma unroll
        for (int nt = 0; nt < 8; nt++)
#pragma unroll
            for (int q = 0; q < 4; q++) acc[f][nt][q] = 0.f;
    float wsum[4] = {0.f, 0.f, 0.f, 0.f};

    FILLJ(0, 0);
    FILLJ(1, 1);
    FILLS(0, 0);
    FILLS(1, 1);

    for (int t = 0; t < N_ / TJ; t++) {
        const int buf = t & 1;
        if (t < N_ / TJ - 1) asm volatile("cp.async.wait_group 1;");
        else                 asm volatile("cp.async.wait_group 0;");
        __syncthreads();

        const unsigned* tile = sWh[buf];
        const float2*   sSt  = sS2[buf];

#pragma unroll 1
        for (int ks = 0; ks < TJ / 8; ks++) {
            const float2 qa = sSt[ks * 8 + tg];
            const float2 qb = sSt[ks * 8 + 4 + tg];

            unsigned af[2][4];
#pragma unroll
            for (int f = 0; f < 2; f++) {
                const int A = f * 2, Bq = f * 2 + 1;
                float w0 = ex2f(fmaxf(s1r[A]  + qa.x, s1q[A]  + qa.y));
                float w1 = ex2f(fmaxf(s1r[Bq] + qa.x, s1q[Bq] + qa.y));
                float w2 = ex2f(fmaxf(s1r[A]  + qb.x, s1q[A]  + qb.y));
                float w3 = ex2f(fmaxf(s1r[Bq] + qb.x, s1q[Bq] + qb.y));
                wsum[A]  += w0 + w2;
                wsum[Bq] += w1 + w3;
                af[f][0] = __float_as_uint(w0) + 0x1000u;  // tf32 round (ALU pipe)
                af[f][1] = __float_as_uint(w1) + 0x1000u;
                af[f][2] = __float_as_uint(w2) + 0x1000u;
                af[f][3] = __float_as_uint(w3) + 0x1000u;
            }

            // B fragments: one LDS.64 per nt gives (k=tg, k=tg+4) pair
            const uint2* bp = (const uint2*)(tile + ks * 512);
            uint2 bf[8];
#pragma unroll
            for (int nt = 0; nt < 8; nt++)
                bf[nt] = bp[(nt * 8 + g) * 4 + tg];

#pragma unroll
            for (int f = 0; f < 2; f++)
#pragma unroll
                for (int nt = 0; nt < 8; nt++) {
                    asm volatile(
                        "mma.sync.aligned.m16n8k8.row.col.f32.tf32.tf32.f32 "
                        "{%0,%1,%2,%3}, {%4,%5,%6,%7}, {%8,%9}, {%0,%1,%2,%3};"
                        : "+f"(acc[f][nt][0]), "+f"(acc[f][nt][1]),
                          "+f"(acc[f][nt][2]), "+f"(acc[f][nt][3])
                        : "r"(af[f][0]), "r"(af[f][1]), "r"(af[f][2]), "r"(af[f][3]),
                          "r"(bf[nt].x), "r"(bf[nt].y));
                }
        }
        __syncthreads();
        if (t + 2 < N_ / TJ) {
            FILLJ(t + 2, buf);
            FILLS(t + 2, buf);
        }
    }

#pragma unroll
    for (int q = 0; q < 4; q++) {
        wsum[q] += __shfl_xor_sync(0xffffffffu, wsum[q], 1);
        wsum[q] += __shfl_xor_sync(0xffffffffu, wsum[q], 2);
    }

#pragma unroll
    for (int q = 0; q < 4; q++) {
        const bool good = mrow[q] && m2ok && (wsum[q] > 0.f);
        const float inv = 1.f / wsum[q];
        const int f = q >> 1;
        const int lohi = (q & 1) * 2;
        float* op = out + ((size_t)(b * N_ + rr[q])) * (H_ * D_) + hh * D_ + tg * 2;
#pragma unroll
        for (int nt = 0; nt < 8; nt++) {
            float2 v;
            v.x = good ? acc[f][nt][lohi + 0] * inv : 0.f;
            v.y = good ? acc[f][nt][lohi + 1] * inv : 0.f;
            *(float2*)(op + nt * 8) = v;
        }
    }
}

// ---------------------------------------------------------------------------
extern "C" void kernel_launch(void* const* d_in, const int* in_sizes, int n_in,
                              void* d_out, int out_size) {
    const float* h    = (const float*)d_in[0];   // [16,1024,256] f32
    const int*   mask = (const int*)  d_in[1];   // [16,1024] i32
    const float* W    = (const float*)d_in[2];   // [256,256] f32
    const float* a    = (const float*)d_in[3];   // [128,1] f32
    float* out = (float*)d_out;                  // [16,1024,256] f32

    cudaFuncSetAttribute(k_gemm_tc,
                         cudaFuncAttributeMaxDynamicSharedMemorySize, GEMM_SMEM);

    int nsplit = (int)((NA4 + NW4 + 255) / 256);
    k_split  <<<nsplit, 256>>>(h, W);
    k_gemm_tc<<<dim3(128, 4), 256, GEMM_SMEM>>>(h, W);
    k_scores <<<64, 256>>>(mask, a);
    k_attn_tc<<<dim3(N_ / 256, BH_), 256>>>(mask, out);
}

// round 17
// speedup vs baseline: 1.2556x; 1.1755x over previous
#include <cuda_runtime.h>
#include <cuda_bf16.h>

#define B_ 16
#define N_ 1024
#define F_ 256
#define H_ 4
#define D_ 64
#define BH_ (B_*H_)
#define NEG_SLOPE 0.2f
#define LOG2E 1.4426950408889634f

// Scratch (allocation-free rule: __device__ globals)
__device__ float    g_Wh[(size_t)BH_ * N_ * D_];  // fp32 Wh
// tf32-bit Wh, interleaved for LDS.64 B-fragments:
// off(j,d) = (j>>3)*512 + d*8 + (j&3)*2 + ((j>>2)&1)   (per bh)
__device__ unsigned g_Wt[(size_t)BH_ * N_ * D_];
__device__ float    g_s1[BH_ * N_];    // s1 * log2e
__device__ float    g_s2[BH_ * N_];    // s2 * log2e
__device__ unsigned g_m2u[BH_];        // order-encoded masked max of s2'
// split-bf16 copies of h and W (hi + lo), filled by k_split
__device__ __nv_bfloat16 g_hA[(size_t)B_ * N_ * F_];
__device__ __nv_bfloat16 g_lA[(size_t)B_ * N_ * F_];
__device__ __nv_bfloat16 g_hW[F_ * F_];
__device__ __nv_bfloat16 g_lW[F_ * F_];

__device__ __forceinline__ float ex2f(float x) {
    float r; asm("ex2.approx.f32 %0, %1;" : "=f"(r) : "f"(x)); return r;
}
__device__ __forceinline__ unsigned cvt_tf32(float x) {
    unsigned r; asm("cvt.rna.tf32.f32 %0, %1;" : "=r"(r) : "f"(x)); return r;
}
__device__ __forceinline__ void cpa16(unsigned dst, const void* src) {
    asm volatile("cp.async.ca.shared.global [%0], [%1], 16;" :: "r"(dst), "l"(src));
}
// monotone float -> unsigned encoding (for atomicMax); 0 reserved as "empty"
__device__ __forceinline__ unsigned encf(float f) {
    int b = __float_as_int(f);
    return (unsigned)b ^ (unsigned)((b >> 31) | 0x80000000);
}

#define MMA_BF16(d, a, b) asm volatile( \
    "mma.sync.aligned.m16n8k16.row.col.f32.bf16.bf16.f32 " \
    "{%0,%1,%2,%3}, {%4,%5,%6,%7}, {%8,%9}, {%0,%1,%2,%3};" \
    : "+f"((d)[0]), "+f"((d)[1]), "+f"((d)[2]), "+f"((d)[3]) \
    : "r"((a)[0]), "r"((a)[1]), "r"((a)[2]), "r"((a)[3]), \
      "r"((b)[0]), "r"((b)[1]))

// ---------------------------------------------------------------------------
// Kernel 0: one-shot split of h and W into bf16 hi/lo pairs + g_m2u reset.
// ---------------------------------------------------------------------------
#define NA4 ((size_t)B_ * N_ * F_ / 4)
#define NW4 ((size_t)F_ * F_ / 4)
__global__ __launch_bounds__(256) void k_split(const float* __restrict__ h,
                                               const float* __restrict__ W) {
    size_t t = (size_t)blockIdx.x * 256 + threadIdx.x;
    if (t < BH_) g_m2u[t] = 0u;           // reset every replay (graph-safe)
    if (t >= NA4 + NW4) return;
    const float4* src; __nv_bfloat16 *dh, *dl; size_t idx;
    if (t < NA4) { src = (const float4*)h; dh = g_hA; dl = g_lA; idx = t; }
    else         { src = (const float4*)W; dh = g_hW; dl = g_lW; idx = t - NA4; }
    float4 v = src[idx];
    float f[4] = {v.x, v.y, v.z, v.w};
    union { __nv_bfloat16 b[4]; uint2 u; } ph, pl;
#pragma unroll
    for (int e = 0; e < 4; e++) {
        __nv_bfloat16 hi = __float2bfloat16(f[e]);
        ph.b[e] = hi;
        pl.b[e] = __float2bfloat16(f[e] - __bfloat162float(hi));
    }
    *(uint2*)(dh + idx * 4) = ph.u;
    *(uint2*)(dl + idx * 4) = pl.u;
}

// ---------------------------------------------------------------------------
// Kernel A: Wh = h @ W^T, split-bf16 3-term MMA, 128x128 block tile.
// grid (128, 2): blockIdx.x = 128-row m-tile, blockIdx.y = head pair.
// 8 warps = 4m x 2n; warp tile 32x64 (warp's n-half == one head).
// 4-stage cp.async pipeline, one __syncthreads per K16 chunk.
// Fused epilogue: fp32 Wh + interleaved tf32 Wt + prescaled s1/s2 +
// per-(bh) masked s2-max via atomicMax on g_m2u.
// Stage (24576 B): AH[128x24] AL[...] BH[128x24] BL[...] bf16, KP=24 pad.
// ---------------------------------------------------------------------------
#define KP 24
#define STG_SZ 24576
#define GEMM_SMEM (4 * STG_SZ + 512)
__global__ __launch_bounds__(256, 2) void k_gemm_tc(const int* __restrict__ mask,
                                                    const float* __restrict__ a) {
    extern __shared__ __align__(16) char smem[];
    float* sa = (float*)(smem + 4 * STG_SZ);   // a * log2e, 128 floats

    const int tid  = threadIdx.x;
    const int warp = tid >> 5, lane = tid & 31;
    const int g  = lane >> 2;
    const int tg = lane & 3;
    const int wm = warp >> 1;        // 0..3 (m)
    const int wn = warp & 1;         // 0..1 (n half == head within pair)
    const int m0 = blockIdx.x * 128;
    const int hp = blockIdx.y;       // head pair
    const unsigned sb = (unsigned)__cvta_generic_to_shared(smem);

    if (tid < 128) sa[tid] = a[tid] * LOG2E;

    // fetch plan: 1024 16B chunks per stage, 4 per thread.
    // region: 0=Ah 1=Al 2=Bh 3=Bl, each 128 rows x 32B real (16 bf16).
    const __nv_bfloat16* fsrc[4];
    unsigned fdst[4];
    {
        const __nv_bfloat16* rb[4] = {
            g_hA + (size_t)m0 * F_, g_lA + (size_t)m0 * F_,
            g_hW + (size_t)hp * 128 * F_, g_lW + (size_t)hp * 128 * F_ };
#pragma unroll
        for (int q = 0; q < 4; q++) {
            int c = tid + 256 * q;           // 0..1023
            int region = c >> 8;
            int cr = c & 255;
            int row = cr >> 1, hf = cr & 1;
            fsrc[q] = rb[region] + (size_t)row * F_ + hf * 8;
            fdst[q] = sb + region * 6144 + row * (KP * 2) + hf * 16;
        }
    }

#define FETCH(kt, st) do {                                          \
        int ko = (kt) * 16;                                         \
        unsigned so = (unsigned)(st) * STG_SZ;                      \
        cpa16(fdst[0] + so, fsrc[0] + ko);                          \
        cpa16(fdst[1] + so, fsrc[1] + ko);                          \
        cpa16(fdst[2] + so, fsrc[2] + ko);                          \
        cpa16(fdst[3] + so, fsrc[3] + ko);                          \
        asm volatile("cp.async.commit_group;");                     \
    } while (0)

    float acc[2][8][4];
#pragma unroll
    for (int mf = 0; mf < 2; mf++)
#pragma unroll
        for (int nf = 0; nf < 8; nf++)
#pragma unroll
            for (int q = 0; q < 4; q++) acc[mf][nf][q] = 0.f;

    FETCH(0, 0);
    FETCH(1, 1);
    FETCH(2, 2);

    for (int kt = 0; kt < 16; kt++) {
        const int st = kt & 3;
        if (kt < 14)       asm volatile("cp.async.wait_group 2;");
        else if (kt == 14) asm volatile("cp.async.wait_group 1;");
        else               asm volatile("cp.async.wait_group 0;");
        __syncthreads();

        const char* stage = smem + st * STG_SZ;
        const __nv_bfloat16* Ah = (const __nv_bfloat16*)(stage);
        const __nv_bfloat16* Al = (const __nv_bfloat16*)(stage + 6144);
        const __nv_bfloat16* Bh = (const __nv_bfloat16*)(stage + 12288);
        const __nv_bfloat16* Bl = (const __nv_bfloat16*)(stage + 18432);
        const int kb = 2 * tg;

        unsigned ah[2][4], al[2][4];
#pragma unroll
        for (int mf = 0; mf < 2; mf++) {
            const int base = (wm * 32 + mf * 16 + g) * KP;
            ah[mf][0] = *(const unsigned*)&Ah[base + kb];
            ah[mf][1] = *(const unsigned*)&Ah[base + 8 * KP + kb];
            ah[mf][2] = *(const unsigned*)&Ah[base + kb + 8];
            ah[mf][3] = *(const unsigned*)&Ah[base + 8 * KP + kb + 8];
            al[mf][0] = *(const unsigned*)&Al[base + kb];
            al[mf][1] = *(const unsigned*)&Al[base + 8 * KP + kb];
            al[mf][2] = *(const unsigned*)&Al[base + kb + 8];
            al[mf][3] = *(const unsigned*)&Al[base + 8 * KP + kb + 8];
        }
        // B in two halves of 4 n-frags to bound register pressure
#pragma unroll
        for (int bhalf = 0; bhalf < 2; bhalf++) {
            unsigned bhv[4][2], blv[4][2];
#pragma unroll
            for (int n4 = 0; n4 < 4; n4++) {
                const int nf = bhalf * 4 + n4;
                const int bb = (wn * 64 + nf * 8 + g) * KP + kb;
                bhv[n4][0] = *(const unsigned*)&Bh[bb];
                bhv[n4][1] = *(const unsigned*)&Bh[bb + 8];
                blv[n4][0] = *(const unsigned*)&Bl[bb];
                blv[n4][1] = *(const unsigned*)&Bl[bb + 8];
            }
#pragma unroll
            for (int mf = 0; mf < 2; mf++)
#pragma unroll
                for (int n4 = 0; n4 < 4; n4++) {
                    float* d = acc[mf][bhalf * 4 + n4];
                    MMA_BF16(d, ah[mf], bhv[n4]);
                    MMA_BF16(d, al[mf], bhv[n4]);
                    MMA_BF16(d, ah[mf], blv[n4]);
                }
        }
        if (kt + 3 < 16) FETCH(kt + 3, (kt + 3) & 3);
    }

    // ---- fused epilogue: Wh stores + Wt interleave + scores + max ----
    const int head = hp * 2 + wn;
    float lmax = -3.0e38f;
#pragma unroll
    for (int mf = 0; mf < 2; mf++) {
        const int rowA = m0 + wm * 32 + mf * 16 + g;
        const int b = rowA >> 10, n = rowA & 1023;
        const int bh = b * H_ + head;
        const size_t base = ((size_t)bh * N_ + n) * D_;
        unsigned* wp = g_Wt + (size_t)bh * N_ * D_
                     + (size_t)(n >> 3) * 512 + (n & 3) * 2 + ((n >> 2) & 1);
        float s1h[2] = {0.f, 0.f}, s2h[2] = {0.f, 0.f};
#pragma unroll
        for (int nf = 0; nf < 8; nf++) {
            const int d = nf * 8 + 2 * tg;
            const float* ac = acc[mf][nf];
            *(float2*)(g_Wh + base + d)          = make_float2(ac[0], ac[1]);
            *(float2*)(g_Wh + base + 8 * D_ + d) = make_float2(ac[2], ac[3]);
            wp[d * 8]           = cvt_tf32(ac[0]);
            wp[d * 8 + 8]       = cvt_tf32(ac[1]);
            wp[512 + d * 8]     = cvt_tf32(ac[2]);
            wp[512 + d * 8 + 8] = cvt_tf32(ac[3]);
            float a1x = sa[d], a1y = sa[d + 1];
            float a2x = sa[64 + d], a2y = sa[64 + d + 1];
            s1h[0] += ac[0] * a1x + ac[1] * a1y;
            s2h[0] += ac[0] * a2x + ac[1] * a2y;
            s1h[1] += ac[2] * a1x + ac[3] * a1y;
            s2h[1] += ac[2] * a2x + ac[3] * a2y;
        }
#pragma unroll
        for (int hh = 0; hh < 2; hh++) {
            s1h[hh] += __shfl_xor_sync(0xffffffffu, s1h[hh], 1);
            s1h[hh] += __shfl_xor_sync(0xffffffffu, s1h[hh], 2);
            s2h[hh] += __shfl_xor_sync(0xffffffffu, s2h[hh], 1);
            s2h[hh] += __shfl_xor_sync(0xffffffffu, s2h[hh], 2);
            const int nn = n + hh * 8;
            if (tg == 0) {
                g_s1[bh * N_ + nn] = s1h[hh];
                g_s2[bh * N_ + nn] = s2h[hh];
            }
            if (mask[b * N_ + nn]) lmax = fmaxf(lmax, s2h[hh]);
        }
    }
    // reduce max across the warp's 8 g-lanes (tg lanes duplicate)
    lmax = fmaxf(lmax, __shfl_xor_sync(0xffffffffu, lmax, 4));
    lmax = fmaxf(lmax, __shfl_xor_sync(0xffffffffu, lmax, 8));
    lmax = fmaxf(lmax, __shfl_xor_sync(0xffffffffu, lmax, 16));
    if (lane == 0 && lmax > -2.9e38f) {
        const int rowA = m0 + wm * 32;
        const int bh = (rowA >> 10) * H_ + head;
        atomicMax(&g_m2u[bh], encf(lmax));
    }
}

// ---------------------------------------------------------------------------
// Kernel C (tensor cores, cp.async pipelined): softmax(P) @ Wh.
// Round-13 configuration (best measured): 2 m-frags/warp, grid (N/256, BH).
// tf32 mma.m16n8k8, LDS.64 B-fragments from interleaved tiles.
// ---------------------------------------------------------------------------
#define TJ 64
#define SZT (TJ * D_ * 4)   // 16384 bytes per buffer
__global__ __launch_bounds__(256, 2) void k_attn_tc(const int* __restrict__ mask,
                                                    float* __restrict__ out) {
    __shared__ __align__(16) unsigned sWh[2][TJ * D_];
    __shared__ __align__(8) float2 sS2[2][TJ];
    const int bh = blockIdx.y, b = bh >> 2, hh = bh & 3;
    const int tid = threadIdx.x;
    const int warp = tid >> 5, lane = tid & 31;
    const int g  = lane >> 2;
    const int tg = lane & 3;
    const int ib = blockIdx.x * 256;
    const unsigned sbW = (unsigned)__cvta_generic_to_shared(sWh);

    const unsigned m2u = g_m2u[bh];
    const bool m2ok = (m2u != 0u);
    const int m2b = (m2u & 0x80000000u) ? (int)(m2u & 0x7FFFFFFFu) : ~(int)m2u;
    const float m2 = m2ok ? __int_as_float(m2b) : 0.f;

    int r0 = ib + warp * 16 + g;
    int rr[4] = { r0, r0 + 8, r0 + 128, r0 + 136 };

    float s1r[4], s1q[4];
    int   mrow[4];
#pragma unroll
    for (int q = 0; q < 4; q++) {
        float s1p = g_s1[bh * N_ + rr[q]];        // prescaled s1*log2e
        float t0 = s1p + m2;
        float rm = fmaxf(t0, NEG_SLOPE * t0);     // rowmax * log2e
        s1r[q] = s1p - rm;
        s1q[q] = fmaf(NEG_SLOPE, s1p, -rm);
        mrow[q] = mask[b * N_ + rr[q]];
    }

    const unsigned* WtB = g_Wt + (size_t)bh * N_ * D_;

#define FILLJ(tile, buf) do {                                              \
        const unsigned* srcW = WtB + (size_t)(tile) * TJ * D_;             \
        _Pragma("unroll")                                                  \
        for (int q = 0; q < 4; q++) {                                      \
            int id = tid + 256 * q;                                        \
            cpa16(sbW + (buf) * SZT + id * 16, srcW + id * 4);             \
        }                                                                  \
        asm volatile("cp.async.commit_group;");                            \
    } while (0)
#define FILLS(tile, buf) do {                                              \
        if (tid < TJ) {                                                    \
            int j = (tile) * TJ + tid;                                     \
            float v = mask[b * N_ + j] ? g_s2[bh * N_ + j] : -1.0e30f;     \
            sS2[buf][tid] = make_float2(v, NEG_SLOPE * v);                 \
        }                                                                  \
    } while (0)

    float acc[2][8][4];
#pragma unroll
    for (int f = 0; f < 2; f++)
#pragma unroll
        for (int nt = 0; nt < 8; nt++)
#pragma unroll
            for (int q = 0; q < 4; q++) acc[f][nt][q] = 0.f;
    float wsum[4] = {0.f, 0.f, 0.f, 0.f};

    FILLJ(0, 0);
    FILLJ(1, 1);
    FILLS(0, 0);
    FILLS(1, 1);

    for (int t = 0; t < N_ / TJ; t++) {
        const int buf = t & 1;
        if (t < N_ / TJ - 1) asm volatile("cp.async.wait_group 1;");
        else                 asm volatile("cp.async.wait_group 0;");
        __syncthreads();

        const unsigned* tile = sWh[buf];
        const float2*   sSt  = sS2[buf];

#pragma unroll 1
        for (int ks = 0; ks < TJ / 8; ks++) {
            const float2 qa = sSt[ks * 8 + tg];
            const float2 qb = sSt[ks * 8 + 4 + tg];

            unsigned af[2][4];
#pragma unroll
            for (int f = 0; f < 2; f++) {
                const int A = f * 2, Bq = f * 2 + 1;
                float w0 = ex2f(fmaxf(s1r[A]  + qa.x, s1q[A]  + qa.y));
                float w1 = ex2f(fmaxf(s1r[Bq] + qa.x, s1q[Bq] + qa.y));
                float w2 = ex2f(fmaxf(s1r[A]  + qb.x, s1q[A]  + qb.y));
                float w3 = ex2f(fmaxf(s1r[Bq] + qb.x, s1q[Bq] + qb.y));
                wsum[A]  += w0 + w2;
                wsum[Bq] += w1 + w3;
                af[f][0] = __float_as_uint(w0) + 0x1000u;  // tf32 round (ALU pipe)
                af[f][1] = __float_as_uint(w1) + 0x1000u;
                af[f][2] = __float_as_uint(w2) + 0x1000u;
                af[f][3] = __float_as_uint(w3) + 0x1000u;
            }

            // B fragments: one LDS.64 per nt gives (k=tg, k=tg+4) pair
            const uint2* bp = (const uint2*)(tile + ks * 512);
            uint2 bf[8];
#pragma unroll
            for (int nt = 0; nt < 8; nt++)
                bf[nt] = bp[(nt * 8 + g) * 4 + tg];

#pragma unroll
            for (int f = 0; f < 2; f++)
#pragma unroll
                for (int nt = 0; nt < 8; nt++) {
                    asm volatile(
                        "mma.sync.aligned.m16n8k8.row.col.f32.tf32.tf32.f32 "
                        "{%0,%1,%2,%3}, {%4,%5,%6,%7}, {%8,%9}, {%0,%1,%2,%3};"
                        : "+f"(acc[f][nt][0]), "+f"(acc[f][nt][1]),
                          "+f"(acc[f][nt][2]), "+f"(acc[f][nt][3])
                        : "r"(af[f][0]), "r"(af[f][1]), "r"(af[f][2]), "r"(af[f][3]),
                          "r"(bf[nt].x), "r"(bf[nt].y));
                }
        }
        __syncthreads();
        if (t + 2 < N_ / TJ) {
            FILLJ(t + 2, buf);
            FILLS(t + 2, buf);
        }
    }

#pragma unroll
    for (int q = 0; q < 4; q++) {
        wsum[q] += __shfl_xor_sync(0xffffffffu, wsum[q], 1);
        wsum[q] += __shfl_xor_sync(0xffffffffu, wsum[q], 2);
    }

#pragma unroll
    for (int q = 0; q < 4; q++) {
        const bool good = mrow[q] && m2ok && (wsum[q] > 0.f);
        const float inv = 1.f / wsum[q];
        const int f = q >> 1;
        const int lohi = (q & 1) * 2;
        float* op = out + ((size_t)(b * N_ + rr[q])) * (H_ * D_) + hh * D_ + tg * 2;
#pragma unroll
        for (int nt = 0; nt < 8; nt++) {
            float2 v;
            v.x = good ? acc[f][nt][lohi + 0] * inv : 0.f;
            v.y = good ? acc[f][nt][lohi + 1] * inv : 0.f;
            *(float2*)(op + nt * 8) = v;
        }
    }
}

// ---------------------------------------------------------------------------
extern "C" void kernel_launch(void* const* d_in, const int* in_sizes, int n_in,
                              void* d_out, int out_size) {
    const float* h    = (const float*)d_in[0];   // [16,1024,256] f32
    const int*   mask = (const int*)  d_in[1];   // [16,1024] i32
    const float* W    = (const float*)d_in[2];   // [256,256] f32
    const float* a    = (const float*)d_in[3];   // [128,1] f32
    float* out = (float*)d_out;                  // [16,1024,256] f32

    cudaFuncSetAttribute(k_gemm_tc,
                         cudaFuncAttributeMaxDynamicSharedMemorySize, GEMM_SMEM);

    int nsplit = (int)((NA4 + NW4 + 255) / 256);
    k_split  <<<nsplit, 256>>>(h, W);
    k_gemm_tc<<<dim3(128, 2), 256, GEMM_SMEM>>>(mask, a);
    k_attn_tc<<<dim3(N_ / 256, BH_), 256>>>(mask, out);
}